// round 2
// baseline (speedup 1.0000x reference)
#include <cuda_runtime.h>
#include <math.h>

#define EPS 1e-5f

#define FMA2(d, a, b) asm("fma.rn.f32x2 %0, %1, %2, %0;" : "+l"(d) : "l"(a), "l"(b))

__device__ __forceinline__ float2 unpack2(unsigned long long v) {
    float2 f;
    asm("mov.b64 {%0,%1}, %2;" : "=f"(f.x), "=f"(f.y) : "l"(v));
    return f;
}

// ---------------- scratch pool (floats) ----------------
#define OF_VOLA   0ull
#define OF_VOLB   25165824ull
#define OF_QKV    50331648ull
#define OF_XATT   88080384ull
#define OF_AOUT   100663296ull
#define OF_VOLP   113246208ull
#define OF_YV     125829120ull
#define OF_S12    138412032ull
#define OF_PCS    139984896ull
#define OF_PCQ    140771328ull
#define OF_PPOOL  141557760ull
#define OF_P12S   142344192ull
#define OF_P12Q   142368768ull
#define OF_PYS    142393344ull
#define OF_PYQ    142589952ull
#define OF_M1     142786560ull
#define OF_R1     142787328ull
#define OF_POOLED 142788096ull
#define OF_M2     142788864ull
#define OF_R2     142788912ull
#define OF_M3     142788960ull
#define OF_R3     142789344ull
#define OF_GATE   142789728ull

__device__ float g_pool[142800000];

__device__ __forceinline__ float geluf(float x) {
    return 0.5f * x * (1.0f + erff(x * 0.70710678118654752f));
}

__device__ __forceinline__ int spatial_of_row(int row) {
    int win = row >> 6, n = row & 63;
    int b = win >> 9, d = (win >> 6) & 7, h = (win >> 3) & 7, w = win & 7;
    int wd = n >> 4, wh = (n >> 2) & 3, ww = n & 3;
    int Z = d * 4 + wd, Y = h * 4 + wh, X = w * 4 + ww;
    return ((b * 32 + Z) * 32 + Y) * 32 + X;
}

// ============================================================
// K1: fused embed GEMM + two LayerNorms (FFMA2 inner loop)
// ============================================================
__global__ __launch_bounds__(288) void k_embed(
    const float* __restrict__ x,
    const float* __restrict__ w1, const float* __restrict__ b1,
    const float* __restrict__ ga, const float* __restrict__ ba,
    const float* __restrict__ w2, const float* __restrict__ b2,
    const float* __restrict__ gc, const float* __restrict__ bc)
{
    __shared__ union {
        struct { float2 sA2[16][32]; float sW[16][288]; } s;
        float sOut[32][288];
    } sm;
    const int tid = threadIdx.x;
    const int row0 = blockIdx.x * 32;
    const int rg = tid / 36, cg = tid % 36;
    unsigned long long acc[4][4];
#pragma unroll
    for (int i = 0; i < 4; i++)
#pragma unroll
        for (int j = 0; j < 4; j++) acc[i][j] = 0ull;

    for (int kb = 0; kb < 192; kb += 16) {
        if (tid < 128) {
            int r = tid >> 2, q = tid & 3;
            float4 v = *(const float4*)(x + (size_t)(row0 + r) * 192 + kb + q * 4);
            sm.s.sA2[q * 4 + 0][r] = make_float2(v.x, v.x);
            sm.s.sA2[q * 4 + 1][r] = make_float2(v.y, v.y);
            sm.s.sA2[q * 4 + 2][r] = make_float2(v.z, v.z);
            sm.s.sA2[q * 4 + 3][r] = make_float2(v.w, v.w);
        }
#pragma unroll
        for (int i = 0; i < 4; i++) {
            int lin = tid + i * 288; int k = lin / 72; int c = (lin % 72) * 4;
            float4 v;
            if (c < 96) v = *(const float4*)(w1 + (size_t)(kb + k) * 96 + c);
            else        v = *(const float4*)(w2 + (size_t)(kb + k) * 192 + (c - 96));
            *(float4*)&sm.s.sW[k][c] = v;
        }
        __syncthreads();
#pragma unroll
        for (int k = 0; k < 16; k++) {
            ulonglong2 a01 = *(const ulonglong2*)&sm.s.sA2[k][rg * 4];
            ulonglong2 a23 = *(const ulonglong2*)&sm.s.sA2[k][rg * 4 + 2];
            const ulonglong2* pw = (const ulonglong2*)&sm.s.sW[k][cg * 8];
            ulonglong2 w01 = pw[0], w23 = pw[1];
            FMA2(acc[0][0], a01.x, w01.x); FMA2(acc[0][1], a01.x, w01.y);
            FMA2(acc[0][2], a01.x, w23.x); FMA2(acc[0][3], a01.x, w23.y);
            FMA2(acc[1][0], a01.y, w01.x); FMA2(acc[1][1], a01.y, w01.y);
            FMA2(acc[1][2], a01.y, w23.x); FMA2(acc[1][3], a01.y, w23.y);
            FMA2(acc[2][0], a23.x, w01.x); FMA2(acc[2][1], a23.x, w01.y);
            FMA2(acc[2][2], a23.x, w23.x); FMA2(acc[2][3], a23.x, w23.y);
            FMA2(acc[3][0], a23.y, w01.x); FMA2(acc[3][1], a23.y, w01.y);
            FMA2(acc[3][2], a23.y, w23.x); FMA2(acc[3][3], a23.y, w23.y);
        }
        __syncthreads();
    }
#pragma unroll
    for (int i = 0; i < 4; i++) {
        int r = rg * 4 + i;
#pragma unroll
        for (int j = 0; j < 4; j++) {
            int c = cg * 8 + j * 2;
            float2 f = unpack2(acc[i][j]);
            float bx = (c < 96) ? b1[c] : b2[c - 96];
            float by = (c + 1 < 96) ? b1[c + 1] : b2[c + 1 - 96];
            sm.sOut[r][c] = f.x + bx;
            sm.sOut[r][c + 1] = f.y + by;
        }
    }
    __syncthreads();

    int warp = tid >> 5, lane = tid & 31; // 9 warps
    for (int r = warp; r < 32; r += 9) {
        int row = row0 + r;
        float s = 0.f, q = 0.f;
#pragma unroll
        for (int i = 0; i < 3; i++) { float v = sm.sOut[r][lane + 32 * i]; s += v; q += v * v; }
#pragma unroll
        for (int o = 16; o; o >>= 1) { s += __shfl_xor_sync(~0u, s, o); q += __shfl_xor_sync(~0u, q, o); }
        float m = s * (1.f / 96.f);
        float rs = rsqrtf(fmaxf(q * (1.f / 96.f) - m * m, 0.f) + EPS);
        float* xao = g_pool + OF_XATT + (size_t)row * 96;
#pragma unroll
        for (int i = 0; i < 3; i++) {
            int c = lane + 32 * i;
            xao[c] = (sm.sOut[r][c] - m) * rs * ga[c] + ba[c];
        }
        s = 0.f; q = 0.f;
#pragma unroll
        for (int i = 0; i < 6; i++) { float v = sm.sOut[r][96 + lane + 32 * i]; s += v; q += v * v; }
#pragma unroll
        for (int o = 16; o; o >>= 1) { s += __shfl_xor_sync(~0u, s, o); q += __shfl_xor_sync(~0u, q, o); }
        m = s * (1.f / 192.f);
        rs = rsqrtf(fmaxf(q * (1.f / 192.f) - m * m, 0.f) + EPS);
        float* va = g_pool + OF_VOLA + (size_t)spatial_of_row(row) * 192;
#pragma unroll
        for (int i = 0; i < 6; i++) {
            int c = lane + 32 * i;
            va[c] = (sm.sOut[r][96 + c] - m) * rs * gc[c] + bc[c];
        }
    }
}

// ============================================================
// K2: depthwise conv 3x3x3 + bias, partial stats
// ============================================================
__global__ __launch_bounds__(192) void k_dwconv(
    const float* __restrict__ dww, const float* __restrict__ dwb)
{
    const float* vin = g_pool + OF_VOLA;
    float* vout = g_pool + OF_VOLB;
    int c = threadIdx.x;
    int blk = blockIdx.x;
    int b = blk >> 10, z = (blk >> 5) & 31, y = blk & 31;

    float w[27];
#pragma unroll
    for (int i = 0; i < 27; i++) w[i] = dww[c * 27 + i];
    float bias = dwb[c];

    const float* lbase[9];
    bool lv[9];
#pragma unroll
    for (int dz = 0; dz < 3; dz++)
#pragma unroll
        for (int dy = 0; dy < 3; dy++) {
            int l = dz * 3 + dy;
            int zz = z + dz - 1, yy = y + dy - 1;
            lv[l] = (zz >= 0 && zz < 32 && yy >= 0 && yy < 32);
            lbase[l] = vin + ((size_t)((b * 32 + zz) * 32 + yy) * 32) * 192 + c;
        }
    float p0[9], p1[9];
#pragma unroll
    for (int l = 0; l < 9; l++) { p0[l] = 0.f; p1[l] = lv[l] ? lbase[l][0] : 0.f; }

    float ssum = 0.f, ssq = 0.f;
    float* orow = vout + ((size_t)blk * 32) * 192 + c;
    for (int xx = 0; xx < 32; xx++) {
        float p2[9];
#pragma unroll
        for (int l = 0; l < 9; l++)
            p2[l] = (lv[l] && xx + 1 < 32) ? lbase[l][(size_t)(xx + 1) * 192] : 0.f;
        float a = bias;
#pragma unroll
        for (int l = 0; l < 9; l++)
            a += w[l * 3 + 0] * p0[l] + w[l * 3 + 1] * p1[l] + w[l * 3 + 2] * p2[l];
        orow[(size_t)xx * 192] = a;
        ssum += a; ssq += a * a;
#pragma unroll
        for (int l = 0; l < 9; l++) { p0[l] = p1[l]; p1[l] = p2[l]; }
    }
    g_pool[OF_PCS + (size_t)blk * 192 + c] = ssum;
    g_pool[OF_PCQ + (size_t)blk * 192 + c] = ssq;
}

// ============================================================
// reductions
// ============================================================
__global__ __launch_bounds__(128) void k_redstats(
    unsigned long long ofs, unsigned long long ofq, int nchunk, int C, float invN,
    unsigned long long ofm, unsigned long long ofr)
{
    __shared__ float ss[128], qq[128];
    int g = blockIdx.x; int b = g / C, c = g % C;
    float s = 0.f, q = 0.f;
    for (int i = threadIdx.x; i < nchunk; i += 128) {
        size_t o = ((size_t)b * nchunk + i) * C + c;
        s += g_pool[ofs + o]; q += g_pool[ofq + o];
    }
    ss[threadIdx.x] = s; qq[threadIdx.x] = q; __syncthreads();
    for (int o = 64; o; o >>= 1) {
        if (threadIdx.x < o) { ss[threadIdx.x] += ss[threadIdx.x + o]; qq[threadIdx.x] += qq[threadIdx.x + o]; }
        __syncthreads();
    }
    if (threadIdx.x == 0) {
        float m = ss[0] * invN;
        g_pool[ofm + g] = m;
        g_pool[ofr + g] = rsqrtf(fmaxf(qq[0] * invN - m * m, 0.f) + EPS);
    }
}

__global__ __launch_bounds__(128) void k_redmean(
    unsigned long long ofs, int nchunk, int C, float invN, unsigned long long ofm)
{
    __shared__ float ss[128];
    int g = blockIdx.x; int b = g / C, c = g % C;
    float s = 0.f;
    for (int i = threadIdx.x; i < nchunk; i += 128)
        s += g_pool[ofs + ((size_t)b * nchunk + i) * C + c];
    ss[threadIdx.x] = s; __syncthreads();
    for (int o = 64; o; o >>= 1) {
        if (threadIdx.x < o) ss[threadIdx.x] += ss[threadIdx.x + o];
        __syncthreads();
    }
    if (threadIdx.x == 0) g_pool[ofm + g] = ss[0] * invN;
}

// ============================================================
// K4: instance norm + gelu in place + pooled partials
// ============================================================
__global__ __launch_bounds__(192) void k_normgelu()
{
    int c = threadIdx.x;
    int blk = blockIdx.x; int b = blk >> 10;
    float m = g_pool[OF_M1 + b * 192 + c], rs = g_pool[OF_R1 + b * 192 + c];
    float* v = g_pool + OF_VOLB + ((size_t)blk * 32) * 192 + c;
    float s = 0.f;
    for (int xx = 0; xx < 32; xx++) {
        float t = (v[(size_t)xx * 192] - m) * rs;
        t = geluf(t);
        v[(size_t)xx * 192] = t;
        s += t;
    }
    g_pool[OF_PPOOL + (size_t)blk * 192 + c] = s;
}

// ============================================================
// K5: ci MLP
// ============================================================
__global__ __launch_bounds__(96) void k_ci(
    const float* __restrict__ w1, const float* __restrict__ b1,
    const float* __restrict__ w2, const float* __restrict__ b2, int nb)
{
    __shared__ float t24[24];
    int tid = threadIdx.x;
    for (int b = 0; b < nb; b++) {
        if (tid < 24) {
            float s = b1[tid];
            for (int c = 0; c < 192; c++) s += g_pool[OF_POOLED + b * 192 + c] * w1[c * 24 + tid];
            t24[tid] = geluf(s);
        }
        __syncthreads();
        {
            float s = b2[tid];
#pragma unroll
            for (int j = 0; j < 24; j++) s += t24[j] * w2[j * 96 + tid];
            g_pool[OF_GATE + b * 96 + tid] = 1.f / (1.f + expf(-s));
        }
        __syncthreads();
    }
}

// ============================================================
// K6: pj conv1x1 (FFMA2)
// ============================================================
__global__ __launch_bounds__(192) void k_pj(
    const float* __restrict__ pw, const float* __restrict__ pb)
{
    __shared__ float2 sA2[16][32];
    __shared__ float sW[16][96];
    int tid = threadIdx.x;
    int row0 = blockIdx.x * 32;
    int rg = tid / 24, cg = tid % 24;
    unsigned long long acc[4][2];
#pragma unroll
    for (int i = 0; i < 4; i++) { acc[i][0] = 0ull; acc[i][1] = 0ull; }
    const float* vb = g_pool + OF_VOLB;
    for (int kb = 0; kb < 192; kb += 16) {
        if (tid < 128) {
            int r = tid >> 2, q = tid & 3;
            float4 v = *(const float4*)(vb + (size_t)spatial_of_row(row0 + r) * 192 + kb + q * 4);
            sA2[q * 4 + 0][r] = make_float2(v.x, v.x);
            sA2[q * 4 + 1][r] = make_float2(v.y, v.y);
            sA2[q * 4 + 2][r] = make_float2(v.z, v.z);
            sA2[q * 4 + 3][r] = make_float2(v.w, v.w);
        }
#pragma unroll
        for (int i = 0; i < 2; i++) {
            int lin = tid + i * 192; int k = lin / 24; int c = (lin % 24) * 4;
            *(float4*)&sW[k][c] = *(const float4*)(pw + (size_t)(kb + k) * 96 + c);
        }
        __syncthreads();
#pragma unroll
        for (int k = 0; k < 16; k++) {
            ulonglong2 a01 = *(const ulonglong2*)&sA2[k][rg * 4];
            ulonglong2 a23 = *(const ulonglong2*)&sA2[k][rg * 4 + 2];
            ulonglong2 w01 = *(const ulonglong2*)&sW[k][cg * 4];
            FMA2(acc[0][0], a01.x, w01.x); FMA2(acc[0][1], a01.x, w01.y);
            FMA2(acc[1][0], a01.y, w01.x); FMA2(acc[1][1], a01.y, w01.y);
            FMA2(acc[2][0], a23.x, w01.x); FMA2(acc[2][1], a23.x, w01.y);
            FMA2(acc[3][0], a23.y, w01.x); FMA2(acc[3][1], a23.y, w01.y);
        }
        __syncthreads();
    }
    float* vp = g_pool + OF_VOLP;
#pragma unroll
    for (int i = 0; i < 4; i++) {
        int row = row0 + rg * 4 + i;
#pragma unroll
        for (int j = 0; j < 2; j++) {
            int c = cg * 4 + j * 2;
            float2 f = unpack2(acc[i][j]);
            float2 o = make_float2(f.x + pb[c], f.y + pb[c + 1]);
            *(float2*)&vp[(size_t)row * 96 + c] = o;
        }
    }
}

// ============================================================
// K7a: qkv GEMM (FFMA2)
// ============================================================
__global__ __launch_bounds__(288) void k_qkv(
    const float* __restrict__ w, const float* __restrict__ bias)
{
    __shared__ float2 sA2[16][32];
    __shared__ float sW[16][288];
    int tid = threadIdx.x;
    int row0 = blockIdx.x * 32;
    int rg = tid / 36, cg = tid % 36;
    unsigned long long acc[4][4];
#pragma unroll
    for (int i = 0; i < 4; i++)
#pragma unroll
        for (int j = 0; j < 4; j++) acc[i][j] = 0ull;
    const float* A = g_pool + OF_XATT;
    for (int kb = 0; kb < 96; kb += 16) {
        if (tid < 128) {
            int r = tid >> 2, q = tid & 3;
            float4 v = *(const float4*)(A + (size_t)(row0 + r) * 96 + kb + q * 4);
            sA2[q * 4 + 0][r] = make_float2(v.x, v.x);
            sA2[q * 4 + 1][r] = make_float2(v.y, v.y);
            sA2[q * 4 + 2][r] = make_float2(v.z, v.z);
            sA2[q * 4 + 3][r] = make_float2(v.w, v.w);
        }
#pragma unroll
        for (int i = 0; i < 4; i++) {
            int lin = tid + i * 288; int k = lin / 72; int c = (lin % 72) * 4;
            *(float4*)&sW[k][c] = *(const float4*)(w + (size_t)(kb + k) * 288 + c);
        }
        __syncthreads();
#pragma unroll
        for (int k = 0; k < 16; k++) {
            ulonglong2 a01 = *(const ulonglong2*)&sA2[k][rg * 4];
            ulonglong2 a23 = *(const ulonglong2*)&sA2[k][rg * 4 + 2];
            const ulonglong2* pw = (const ulonglong2*)&sW[k][cg * 8];
            ulonglong2 w01 = pw[0], w23 = pw[1];
            FMA2(acc[0][0], a01.x, w01.x); FMA2(acc[0][1], a01.x, w01.y);
            FMA2(acc[0][2], a01.x, w23.x); FMA2(acc[0][3], a01.x, w23.y);
            FMA2(acc[1][0], a01.y, w01.x); FMA2(acc[1][1], a01.y, w01.y);
            FMA2(acc[1][2], a01.y, w23.x); FMA2(acc[1][3], a01.y, w23.y);
            FMA2(acc[2][0], a23.x, w01.x); FMA2(acc[2][1], a23.x, w01.y);
            FMA2(acc[2][2], a23.x, w23.x); FMA2(acc[2][3], a23.x, w23.y);
            FMA2(acc[3][0], a23.y, w01.x); FMA2(acc[3][1], a23.y, w01.y);
            FMA2(acc[3][2], a23.y, w23.x); FMA2(acc[3][3], a23.y, w23.y);
        }
        __syncthreads();
    }
    float* Q = g_pool + OF_QKV;
#pragma unroll
    for (int i = 0; i < 4; i++) {
        int row = row0 + rg * 4 + i;
#pragma unroll
        for (int j = 0; j < 4; j++) {
            int c = cg * 8 + j * 2;
            float2 f = unpack2(acc[i][j]);
            float2 o = make_float2(f.x + bias[c], f.y + bias[c + 1]);
            *(float2*)&Q[(size_t)row * 288 + c] = o;
        }
    }
}

// ============================================================
// K7b: attention per window (FFMA2 in QK and PV)
// ============================================================
__global__ __launch_bounds__(256) void k_attn(const float* __restrict__ rpb)
{
    __shared__ float qS[64][18], kS[64][18], vS[64][20];
    __shared__ float2 pS2[64][65];
    int tid = threadIdx.x;
    int win = blockIdx.x; int b = win >> 9;
    const float* qkv = g_pool + OF_QKV + (size_t)win * 64 * 288;
    float* out = g_pool + OF_AOUT + (size_t)win * 64 * 96;
    int warp = tid >> 5, lane = tid & 31;

    for (int hh = 0; hh < 6; hh++) {
        __syncthreads();
#pragma unroll
        for (int i = 0; i < 4; i++) {
            int idx = tid + i * 256; int n = idx >> 4, d = idx & 15;
            size_t base = (size_t)n * 288 + hh * 16 + d;
            qS[n][d] = qkv[base] * 0.25f;
            kS[n][d] = qkv[base + 96];
            vS[n][d] = qkv[base + 192] * g_pool[OF_GATE + b * 96 + hh * 16 + d];
        }
        __syncthreads();
        for (int rr = 0; rr < 8; rr++) {
            int n = warp * 8 + rr;
            int nd = n >> 4, nh = (n >> 2) & 3, nw = n & 3;
            int m0 = lane, m1 = lane + 32;
            unsigned long long s0a = 0ull, s1a = 0ull;
#pragma unroll
            for (int d2 = 0; d2 < 8; d2++) {
                unsigned long long q2 = *(const unsigned long long*)&qS[n][d2 * 2];
                unsigned long long k0 = *(const unsigned long long*)&kS[m0][d2 * 2];
                unsigned long long k1 = *(const unsigned long long*)&kS[m1][d2 * 2];
                FMA2(s0a, q2, k0);
                FMA2(s1a, q2, k1);
            }
            float2 f0 = unpack2(s0a), f1 = unpack2(s1a);
            float s0 = f0.x + f0.y, s1 = f1.x + f1.y;
            {
                int md = m0 >> 4, mh = (m0 >> 2) & 3, mw = m0 & 3;
                s0 += rpb[((nd - md + 3) * 49 + (nh - mh + 3) * 7 + (nw - mw + 3)) * 6 + hh];
                md = m1 >> 4; mh = (m1 >> 2) & 3; mw = m1 & 3;
                s1 += rpb[((nd - md + 3) * 49 + (nh - mh + 3) * 7 + (nw - mw + 3)) * 6 + hh];
            }
            float mx = fmaxf(s0, s1);
#pragma unroll
            for (int o = 16; o; o >>= 1) mx = fmaxf(mx, __shfl_xor_sync(~0u, mx, o));
            float e0 = expf(s0 - mx), e1 = expf(s1 - mx);
            float sum = e0 + e1;
#pragma unroll
            for (int o = 16; o; o >>= 1) sum += __shfl_xor_sync(~0u, sum, o);
            float inv = 1.f / sum;
            float p0 = e0 * inv, p1 = e1 * inv;
            pS2[n][m0] = make_float2(p0, p0);
            pS2[n][m1] = make_float2(p1, p1);
        }
        __syncthreads();
        {
            int n = tid >> 2, dg = tid & 3;
            unsigned long long a01 = 0ull, a23 = 0ull;
#pragma unroll
            for (int m = 0; m < 64; m++) {
                unsigned long long pm = *(const unsigned long long*)&pS2[n][m];
                ulonglong2 v2 = *(const ulonglong2*)&vS[m][dg * 4];
                FMA2(a01, pm, v2.x);
                FMA2(a23, pm, v2.y);
            }
            float2 f01 = unpack2(a01), f23 = unpack2(a23);
            size_t ob = (size_t)n * 96 + hh * 16 + dg * 4;
            *(float4*)(out + ob) = make_float4(f01.x, f01.y, f23.x, f23.y);
        }
    }
}

// ============================================================
// K8a: si stage 1
// ============================================================
__global__ __launch_bounds__(256) void k_si1(
    const float* __restrict__ w1, const float* __restrict__ b1)
{
    __shared__ float aS[64][97];
    __shared__ float wS[96 * 12];
    __shared__ float sb[64][12];
    int tid = threadIdx.x;
    int blk = blockIdx.x; int row0 = blk * 64;
    const float* A = g_pool + OF_AOUT;
    for (int i = tid; i < 96 * 12; i += 256) wS[i] = w1[i];
    for (int i = tid; i < 64 * 96; i += 256) {
        int r = i / 96, c = i % 96;
        aS[r][c] = A[(size_t)(row0 + r) * 96 + c];
    }
    __syncthreads();
    if (tid < 64) {
        float s[12];
#pragma unroll
        for (int j = 0; j < 12; j++) s[j] = b1[j];
        for (int c = 0; c < 96; c++) {
            float a = aS[tid][c];
#pragma unroll
            for (int j = 0; j < 12; j++) s[j] += a * wS[c * 12 + j];
        }
        float* o = g_pool + OF_S12 + (size_t)(row0 + tid) * 12;
#pragma unroll
        for (int j = 0; j < 12; j++) { o[j] = s[j]; sb[tid][j] = s[j]; }
    }
    __syncthreads();
    if (tid < 12) {
        float S = 0.f, Q = 0.f;
        for (int r = 0; r < 64; r++) { float v = sb[r][tid]; S += v; Q += v * v; }
        g_pool[OF_P12S + (size_t)blk * 12 + tid] = S;
        g_pool[OF_P12Q + (size_t)blk * 12 + tid] = Q;
    }
}

// ============================================================
// K8c: gate + multiply + partials
// ============================================================
__global__ __launch_bounds__(96) void k_gatemul(
    const float* __restrict__ w2, const float* __restrict__ b2)
{
    __shared__ float gb[64];
    int tid = threadIdx.x;
    int blk = blockIdx.x; int row0 = blk * 64; int b = row0 >> 15;
    if (tid < 64) {
        const float* s = g_pool + OF_S12 + (size_t)(row0 + tid) * 12;
        float a = b2[0];
#pragma unroll
        for (int j = 0; j < 12; j++) {
            float v = (s[j] - g_pool[OF_M2 + b * 12 + j]) * g_pool[OF_R2 + b * 12 + j];
            a += geluf(v) * w2[j];
        }
        gb[tid] = 1.f / (1.f + expf(-a));
    }
    __syncthreads();
    const float* vp = g_pool + OF_VOLP + (size_t)row0 * 96 + tid;
    float* yv = g_pool + OF_YV + (size_t)row0 * 96 + tid;
    float ss = 0.f, sq = 0.f;
    for (int r = 0; r < 64; r++) {
        float y = gb[r] * vp[(size_t)r * 96];
        yv[(size_t)r * 96] = y;
        ss += y; sq += y * y;
    }
    g_pool[OF_PYS + (size_t)blk * 96 + tid] = ss;
    g_pool[OF_PYQ + (size_t)blk * 96 + tid] = sq;
}

// ============================================================
// K9: final: [LN(attn) | inorm(y)] @ w_proj + b  (FFMA2, dyn smem)
// ============================================================
__global__ __launch_bounds__(192) void k_final(
    const float* __restrict__ wp, const float* __restrict__ bp,
    const float* __restrict__ ga, const float* __restrict__ ba,
    float* __restrict__ out)
{
    extern __shared__ float dynsm[];
    float2 (*sAT2)[36] = (float2(*)[36])dynsm;                 // 192 x 36 float2 = 55296B
    float (*sW)[192] = (float(*)[192])(dynsm + 13824);         // 16 x 192 float = 12288B
    int tid = threadIdx.x;
    int row0 = blockIdx.x * 32; int b = row0 >> 15;
    const float* A = g_pool + OF_AOUT;
    for (int i = 0; i < 16; i++) {
        int idx = tid + i * 192; int r = idx / 96, c = idx % 96;
        float v = A[(size_t)(row0 + r) * 96 + c];
        sAT2[c][r] = make_float2(v, v);
    }
    __syncthreads();
    int warp = tid >> 5, lane = tid & 31; // 6 warps
    for (int r = warp; r < 32; r += 6) {
        float s = 0.f, q = 0.f;
#pragma unroll
        for (int i = 0; i < 3; i++) { float v = sAT2[lane + 32 * i][r].x; s += v; q += v * v; }
#pragma unroll
        for (int o = 16; o; o >>= 1) { s += __shfl_xor_sync(~0u, s, o); q += __shfl_xor_sync(~0u, q, o); }
        float m = s * (1.f / 96.f);
        float rs = rsqrtf(fmaxf(q * (1.f / 96.f) - m * m, 0.f) + EPS);
#pragma unroll
        for (int i = 0; i < 3; i++) {
            int c = lane + 32 * i;
            float v = (sAT2[c][r].x - m) * rs * ga[c] + ba[c];
            sAT2[c][r] = make_float2(v, v);
        }
    }
    const float* Y = g_pool + OF_YV;
    for (int i = 0; i < 16; i++) {
        int idx = tid + i * 192; int r = idx / 96, c = idx % 96;
        float v = (Y[(size_t)(row0 + r) * 96 + c] - g_pool[OF_M3 + b * 96 + c]) * g_pool[OF_R3 + b * 96 + c];
        sAT2[96 + c][r] = make_float2(v, v);
    }
    __syncthreads();

    int rg = tid / 24, cg = tid % 24;
    unsigned long long acc[4][4];
#pragma unroll
    for (int i = 0; i < 4; i++)
#pragma unroll
        for (int j = 0; j < 4; j++) acc[i][j] = 0ull;
    for (int kb = 0; kb < 192; kb += 16) {
#pragma unroll
        for (int i = 0; i < 4; i++) {
            int lin = tid + i * 192; int k = lin / 48; int c = (lin % 48) * 4;
            *(float4*)&sW[k][c] = *(const float4*)(wp + (size_t)(kb + k) * 192 + c);
        }
        __syncthreads();
#pragma unroll
        for (int k = 0; k < 16; k++) {
            ulonglong2 a01 = *(const ulonglong2*)&sAT2[kb + k][rg * 4];
            ulonglong2 a23 = *(const ulonglong2*)&sAT2[kb + k][rg * 4 + 2];
            const ulonglong2* pw = (const ulonglong2*)&sW[k][cg * 8];
            ulonglong2 w01 = pw[0], w23 = pw[1];
            FMA2(acc[0][0], a01.x, w01.x); FMA2(acc[0][1], a01.x, w01.y);
            FMA2(acc[0][2], a01.x, w23.x); FMA2(acc[0][3], a01.x, w23.y);
            FMA2(acc[1][0], a01.y, w01.x); FMA2(acc[1][1], a01.y, w01.y);
            FMA2(acc[1][2], a01.y, w23.x); FMA2(acc[1][3], a01.y, w23.y);
            FMA2(acc[2][0], a23.x, w01.x); FMA2(acc[2][1], a23.x, w01.y);
            FMA2(acc[2][2], a23.x, w23.x); FMA2(acc[2][3], a23.x, w23.y);
            FMA2(acc[3][0], a23.y, w01.x); FMA2(acc[3][1], a23.y, w01.y);
            FMA2(acc[3][2], a23.y, w23.x); FMA2(acc[3][3], a23.y, w23.y);
        }
        __syncthreads();
    }
#pragma unroll
    for (int i = 0; i < 4; i++) {
        int row = row0 + rg * 4 + i;
#pragma unroll
        for (int j = 0; j < 4; j++) {
            int c = cg * 8 + j * 2;
            float2 f = unpack2(acc[i][j]);
            float2 o = make_float2(f.x + bp[c], f.y + bp[c + 1]);
            *(float2*)&out[(size_t)row * 192 + c] = o;
        }
    }
}

// ============================================================
// host launcher
// ============================================================
extern "C" void kernel_launch(void* const* d_in, const int* in_sizes, int n_in,
                              void* d_out, int out_size)
{
    const float* x       = (const float*)d_in[0];
    const float* w_pattn = (const float*)d_in[1];
    const float* b_pattn = (const float*)d_in[2];
    const float* g_aln   = (const float*)d_in[3];
    const float* b_aln   = (const float*)d_in[4];
    const float* w_pcnn  = (const float*)d_in[5];
    const float* b_pcnn  = (const float*)d_in[6];
    const float* g_cln   = (const float*)d_in[7];
    const float* b_cln   = (const float*)d_in[8];
    const float* dw_w    = (const float*)d_in[9];
    const float* dw_b    = (const float*)d_in[10];
    const float* ci_w1   = (const float*)d_in[11];
    const float* ci_b1   = (const float*)d_in[12];
    const float* ci_w2   = (const float*)d_in[13];
    const float* ci_b2   = (const float*)d_in[14];
    const float* pj_w    = (const float*)d_in[15];
    const float* pj_b    = (const float*)d_in[16];
    const float* qkv_w   = (const float*)d_in[17];
    const float* qkv_b   = (const float*)d_in[18];
    const float* si_w1   = (const float*)d_in[19];
    const float* si_b1   = (const float*)d_in[20];
    const float* si_w2   = (const float*)d_in[21];
    const float* si_b2   = (const float*)d_in[22];
    const float* g_anorm = (const float*)d_in[23];
    const float* b_anorm = (const float*)d_in[24];
    const float* w_proj  = (const float*)d_in[25];
    const float* b_proj  = (const float*)d_in[26];
    const float* rpb     = (const float*)d_in[27];

    const int Bwin = in_sizes[0] / (64 * 192);   // 2048
    const int rows = Bwin * 64;                  // 131072
    const int nb   = Bwin / 512;                 // 4

    cudaFuncSetAttribute(k_final, cudaFuncAttributeMaxDynamicSharedMemorySize, 69632);

    k_embed<<<rows / 32, 288>>>(x, w_pattn, b_pattn, g_aln, b_aln,
                                w_pcnn, b_pcnn, g_cln, b_cln);
    k_dwconv<<<nb * 1024, 192>>>(dw_w, dw_b);
    k_redstats<<<nb * 192, 128>>>(OF_PCS, OF_PCQ, 1024, 192, 1.f / 32768.f, OF_M1, OF_R1);
    k_normgelu<<<nb * 1024, 192>>>();
    k_redmean<<<nb * 192, 128>>>(OF_PPOOL, 1024, 192, 1.f / 32768.f, OF_POOLED);
    k_ci<<<1, 96>>>(ci_w1, ci_b1, ci_w2, ci_b2, nb);
    k_pj<<<rows / 32, 192>>>(pj_w, pj_b);
    k_qkv<<<rows / 32, 288>>>(qkv_w, qkv_b);
    k_attn<<<Bwin, 256>>>(rpb);
    k_si1<<<rows / 64, 256>>>(si_w1, si_b1);
    k_redstats<<<nb * 12, 128>>>(OF_P12S, OF_P12Q, 512, 12, 1.f / 32768.f, OF_M2, OF_R2);
    k_gatemul<<<rows / 64, 96>>>(si_w2, si_b2);
    k_redstats<<<nb * 96, 128>>>(OF_PYS, OF_PYQ, 512, 96, 1.f / 32768.f, OF_M3, OF_R3);
    k_final<<<rows / 32, 192, 67584>>>(w_proj, b_proj, g_anorm, b_anorm, (float*)d_out);
}

// round 3
// speedup vs baseline: 2.0234x; 2.0234x over previous
#include <cuda_runtime.h>
#include <math.h>

#define EPS 1e-5f

// ---------------- scratch pool (floats) ----------------
#define OF_VOLA   0ull
#define OF_VOLB   25165824ull
#define OF_QKV    50331648ull
#define OF_XATT   88080384ull
#define OF_AOUT   100663296ull
#define OF_VOLP   113246208ull
#define OF_YV     125829120ull
#define OF_S12    138412032ull
#define OF_PCS    139984896ull
#define OF_PCQ    140771328ull
#define OF_PPOOL  141557760ull
#define OF_P12S   142344192ull
#define OF_P12Q   142368768ull
#define OF_PYS    142393344ull
#define OF_PYQ    142589952ull
#define OF_M1     142786560ull
#define OF_R1     142787328ull
#define OF_POOLED 142788096ull
#define OF_M2     142788864ull
#define OF_R2     142788912ull
#define OF_M3     142788960ull
#define OF_R3     142789344ull
#define OF_GATE   142789728ull

__device__ float g_pool[142800000];

__device__ __forceinline__ float geluf(float x) {
    return 0.5f * x * (1.0f + erff(x * 0.70710678118654752f));
}

__device__ __forceinline__ float tf32f(float x) {
    unsigned u;
    asm("cvt.rna.tf32.f32 %0, %1;" : "=r"(u) : "f"(x));
    return __uint_as_float(u);
}

__device__ __forceinline__ void mma8(float4& d, unsigned a0, unsigned a1,
                                     unsigned a2, unsigned a3,
                                     unsigned b0, unsigned b1) {
    asm volatile(
        "mma.sync.aligned.m16n8k8.row.col.f32.tf32.tf32.f32 "
        "{%0,%1,%2,%3},{%4,%5,%6,%7},{%8,%9},{%0,%1,%2,%3};"
        : "+f"(d.x), "+f"(d.y), "+f"(d.z), "+f"(d.w)
        : "r"(a0), "r"(a1), "r"(a2), "r"(a3), "r"(b0), "r"(b1));
}

__device__ __forceinline__ int spatial_of_row(int row) {
    int win = row >> 6, n = row & 63;
    int b = win >> 9, d = (win >> 6) & 7, h = (win >> 3) & 7, w = win & 7;
    int wd = n >> 4, wh = (n >> 2) & 3, ww = n & 3;
    int Z = d * 4 + wd, Y = h * 4 + wh, X = w * 4 + ww;
    return ((b * 32 + Z) * 32 + Y) * 32 + X;
}

// ============================================================
// K1: embed GEMM (tf32 mma): X(64,192) @ [w1|w2](192,288) + LNs
// block 256, grid rows/64, dyn smem 73728B
// ============================================================
__global__ __launch_bounds__(256) void k_embed(
    const float* __restrict__ x,
    const float* __restrict__ w1, const float* __restrict__ b1,
    const float* __restrict__ ga, const float* __restrict__ ba,
    const float* __restrict__ w2, const float* __restrict__ b2,
    const float* __restrict__ gc, const float* __restrict__ bc)
{
    extern __shared__ float sm[];
    float (*sA)[36]  = (float(*)[36])sm;                 // 64x36
    float (*sW)[296] = (float(*)[296])(sm + 64 * 36);    // 32x296
    float (*sOut)[288] = (float(*)[288])sm;              // 64x288 (reuse)
    const int tid = threadIdx.x, warp = tid >> 5, lane = tid & 31;
    const int g = lane >> 2, t = lane & 3;
    const int wm = warp >> 1, wn = warp & 1;
    const int row0 = blockIdx.x * 64;
    const int mrow = wm * 16;

    float4 acc[18];
#pragma unroll
    for (int j = 0; j < 18; j++) acc[j] = make_float4(0.f, 0.f, 0.f, 0.f);

    for (int kb = 0; kb < 192; kb += 32) {
#pragma unroll
        for (int i = 0; i < 2; i++) {
            int idx = tid * 2 + i; int r = idx >> 3, c = (idx & 7) * 4;
            float4 v = *(const float4*)(x + (size_t)(row0 + r) * 192 + kb + c);
            sA[r][c] = tf32f(v.x); sA[r][c + 1] = tf32f(v.y);
            sA[r][c + 2] = tf32f(v.z); sA[r][c + 3] = tf32f(v.w);
        }
#pragma unroll
        for (int i = 0; i < 9; i++) {
            int idx = tid + i * 256; int r = idx / 72, c = (idx % 72) * 4;
            float4 v;
            if (c < 96) v = *(const float4*)(w1 + (size_t)(kb + r) * 96 + c);
            else        v = *(const float4*)(w2 + (size_t)(kb + r) * 192 + (c - 96));
            sW[r][c] = tf32f(v.x); sW[r][c + 1] = tf32f(v.y);
            sW[r][c + 2] = tf32f(v.z); sW[r][c + 3] = tf32f(v.w);
        }
        __syncthreads();
#pragma unroll
        for (int sk = 0; sk < 32; sk += 8) {
            unsigned a0 = __float_as_uint(sA[mrow + g][sk + t]);
            unsigned a1 = __float_as_uint(sA[mrow + g + 8][sk + t]);
            unsigned a2 = __float_as_uint(sA[mrow + g][sk + t + 4]);
            unsigned a3 = __float_as_uint(sA[mrow + g + 8][sk + t + 4]);
#pragma unroll
            for (int j = 0; j < 18; j++) {
                int n0 = wn * 144 + j * 8;
                unsigned b0v = __float_as_uint(sW[sk + t][n0 + g]);
                unsigned b1v = __float_as_uint(sW[sk + t + 4][n0 + g]);
                mma8(acc[j], a0, a1, a2, a3, b0v, b1v);
            }
        }
        __syncthreads();
    }
    // write accum + bias to sOut
    {
        int r0 = mrow + g, r1 = r0 + 8;
#pragma unroll
        for (int j = 0; j < 18; j++) {
            int c = wn * 144 + j * 8 + 2 * t;
            float bx = (c < 96) ? b1[c] : b2[c - 96];
            float by = (c + 1 < 96) ? b1[c + 1] : b2[c + 1 - 96];
            sOut[r0][c] = acc[j].x + bx; sOut[r0][c + 1] = acc[j].y + by;
            sOut[r1][c] = acc[j].z + bx; sOut[r1][c + 1] = acc[j].w + by;
        }
    }
    __syncthreads();

    for (int r = warp; r < 64; r += 8) {
        int row = row0 + r;
        float s = 0.f, q = 0.f;
#pragma unroll
        for (int i = 0; i < 3; i++) { float v = sOut[r][lane + 32 * i]; s += v; q += v * v; }
#pragma unroll
        for (int o = 16; o; o >>= 1) { s += __shfl_xor_sync(~0u, s, o); q += __shfl_xor_sync(~0u, q, o); }
        float m = s * (1.f / 96.f);
        float rs = rsqrtf(fmaxf(q * (1.f / 96.f) - m * m, 0.f) + EPS);
        float* xao = g_pool + OF_XATT + (size_t)row * 96;
#pragma unroll
        for (int i = 0; i < 3; i++) {
            int c = lane + 32 * i;
            xao[c] = (sOut[r][c] - m) * rs * ga[c] + ba[c];
        }
        s = 0.f; q = 0.f;
#pragma unroll
        for (int i = 0; i < 6; i++) { float v = sOut[r][96 + lane + 32 * i]; s += v; q += v * v; }
#pragma unroll
        for (int o = 16; o; o >>= 1) { s += __shfl_xor_sync(~0u, s, o); q += __shfl_xor_sync(~0u, q, o); }
        m = s * (1.f / 192.f);
        rs = rsqrtf(fmaxf(q * (1.f / 192.f) - m * m, 0.f) + EPS);
        float* va = g_pool + OF_VOLA + (size_t)spatial_of_row(row) * 192;
#pragma unroll
        for (int i = 0; i < 6; i++) {
            int c = lane + 32 * i;
            va[c] = (sOut[r][96 + c] - m) * rs * gc[c] + bc[c];
        }
    }
}

// ============================================================
// K2: depthwise conv 3x3x3 + bias, partial stats
// ============================================================
__global__ __launch_bounds__(192) void k_dwconv(
    const float* __restrict__ dww, const float* __restrict__ dwb)
{
    const float* vin = g_pool + OF_VOLA;
    float* vout = g_pool + OF_VOLB;
    int c = threadIdx.x;
    int blk = blockIdx.x;
    int b = blk >> 10, z = (blk >> 5) & 31, y = blk & 31;

    float w[27];
#pragma unroll
    for (int i = 0; i < 27; i++) w[i] = dww[c * 27 + i];
    float bias = dwb[c];

    const float* lbase[9];
    bool lv[9];
#pragma unroll
    for (int dz = 0; dz < 3; dz++)
#pragma unroll
        for (int dy = 0; dy < 3; dy++) {
            int l = dz * 3 + dy;
            int zz = z + dz - 1, yy = y + dy - 1;
            lv[l] = (zz >= 0 && zz < 32 && yy >= 0 && yy < 32);
            lbase[l] = vin + ((size_t)((b * 32 + zz) * 32 + yy) * 32) * 192 + c;
        }
    float p0[9], p1[9];
#pragma unroll
    for (int l = 0; l < 9; l++) { p0[l] = 0.f; p1[l] = lv[l] ? lbase[l][0] : 0.f; }

    float ssum = 0.f, ssq = 0.f;
    float* orow = vout + ((size_t)blk * 32) * 192 + c;
    for (int xx = 0; xx < 32; xx++) {
        float p2[9];
#pragma unroll
        for (int l = 0; l < 9; l++)
            p2[l] = (lv[l] && xx + 1 < 32) ? lbase[l][(size_t)(xx + 1) * 192] : 0.f;
        float a = bias;
#pragma unroll
        for (int l = 0; l < 9; l++)
            a += w[l * 3 + 0] * p0[l] + w[l * 3 + 1] * p1[l] + w[l * 3 + 2] * p2[l];
        orow[(size_t)xx * 192] = a;
        ssum += a; ssq += a * a;
#pragma unroll
        for (int l = 0; l < 9; l++) { p0[l] = p1[l]; p1[l] = p2[l]; }
    }
    g_pool[OF_PCS + (size_t)blk * 192 + c] = ssum;
    g_pool[OF_PCQ + (size_t)blk * 192 + c] = ssq;
}

// ============================================================
// reductions
// ============================================================
__global__ __launch_bounds__(128) void k_redstats(
    unsigned long long ofs, unsigned long long ofq, int nchunk, int C, float invN,
    unsigned long long ofm, unsigned long long ofr)
{
    __shared__ float ss[128], qq[128];
    int g = blockIdx.x; int b = g / C, c = g % C;
    float s = 0.f, q = 0.f;
    for (int i = threadIdx.x; i < nchunk; i += 128) {
        size_t o = ((size_t)b * nchunk + i) * C + c;
        s += g_pool[ofs + o]; q += g_pool[ofq + o];
    }
    ss[threadIdx.x] = s; qq[threadIdx.x] = q; __syncthreads();
    for (int o = 64; o; o >>= 1) {
        if (threadIdx.x < o) { ss[threadIdx.x] += ss[threadIdx.x + o]; qq[threadIdx.x] += qq[threadIdx.x + o]; }
        __syncthreads();
    }
    if (threadIdx.x == 0) {
        float m = ss[0] * invN;
        g_pool[ofm + g] = m;
        g_pool[ofr + g] = rsqrtf(fmaxf(qq[0] * invN - m * m, 0.f) + EPS);
    }
}

__global__ __launch_bounds__(128) void k_redmean(
    unsigned long long ofs, int nchunk, int C, float invN, unsigned long long ofm)
{
    __shared__ float ss[128];
    int g = blockIdx.x; int b = g / C, c = g % C;
    float s = 0.f;
    for (int i = threadIdx.x; i < nchunk; i += 128)
        s += g_pool[ofs + ((size_t)b * nchunk + i) * C + c];
    ss[threadIdx.x] = s; __syncthreads();
    for (int o = 64; o; o >>= 1) {
        if (threadIdx.x < o) ss[threadIdx.x] += ss[threadIdx.x + o];
        __syncthreads();
    }
    if (threadIdx.x == 0) g_pool[ofm + g] = ss[0] * invN;
}

// ============================================================
// K4: instance norm + gelu + pooled partials
// ============================================================
__global__ __launch_bounds__(192) void k_normgelu()
{
    int c = threadIdx.x;
    int blk = blockIdx.x; int b = blk >> 10;
    float m = g_pool[OF_M1 + b * 192 + c], rs = g_pool[OF_R1 + b * 192 + c];
    float* v = g_pool + OF_VOLB + ((size_t)blk * 32) * 192 + c;
    float s = 0.f;
    for (int xx = 0; xx < 32; xx++) {
        float t = (v[(size_t)xx * 192] - m) * rs;
        t = geluf(t);
        v[(size_t)xx * 192] = t;
        s += t;
    }
    g_pool[OF_PPOOL + (size_t)blk * 192 + c] = s;
}

// ============================================================
// K5: ci MLP
// ============================================================
__global__ __launch_bounds__(96) void k_ci(
    const float* __restrict__ w1, const float* __restrict__ b1,
    const float* __restrict__ w2, const float* __restrict__ b2, int nb)
{
    __shared__ float t24[24];
    int tid = threadIdx.x;
    for (int b = 0; b < nb; b++) {
        if (tid < 24) {
            float s = b1[tid];
            for (int c = 0; c < 192; c++) s += g_pool[OF_POOLED + b * 192 + c] * w1[c * 24 + tid];
            t24[tid] = geluf(s);
        }
        __syncthreads();
        {
            float s = b2[tid];
#pragma unroll
            for (int j = 0; j < 24; j++) s += t24[j] * w2[j * 96 + tid];
            g_pool[OF_GATE + b * 96 + tid] = 1.f / (1.f + expf(-s));
        }
        __syncthreads();
    }
}

// ============================================================
// K6: pj conv1x1 (tf32 mma): gather(VOLB)(64,192) @ pj_w(192,96)
// block 256, grid rows/64, static smem
// ============================================================
__global__ __launch_bounds__(256) void k_pj(
    const float* __restrict__ pw, const float* __restrict__ pb)
{
    __shared__ float sA[64][36];
    __shared__ float sW[32][104];
    const int tid = threadIdx.x, warp = tid >> 5, lane = tid & 31;
    const int g = lane >> 2, t = lane & 3;
    const int wm = warp >> 1, wn = warp & 1;
    const int row0 = blockIdx.x * 64;
    const int mrow = wm * 16;
    const float* vb = g_pool + OF_VOLB;

    float4 acc[6];
#pragma unroll
    for (int j = 0; j < 6; j++) acc[j] = make_float4(0.f, 0.f, 0.f, 0.f);

    for (int kb = 0; kb < 192; kb += 32) {
#pragma unroll
        for (int i = 0; i < 2; i++) {
            int idx = tid * 2 + i; int r = idx >> 3, c = (idx & 7) * 4;
            float4 v = *(const float4*)(vb + (size_t)spatial_of_row(row0 + r) * 192 + kb + c);
            sA[r][c] = tf32f(v.x); sA[r][c + 1] = tf32f(v.y);
            sA[r][c + 2] = tf32f(v.z); sA[r][c + 3] = tf32f(v.w);
        }
#pragma unroll
        for (int i = 0; i < 3; i++) {
            int idx = tid + i * 256; int r = idx / 24, c = (idx % 24) * 4;
            float4 v = *(const float4*)(pw + (size_t)(kb + r) * 96 + c);
            sW[r][c] = tf32f(v.x); sW[r][c + 1] = tf32f(v.y);
            sW[r][c + 2] = tf32f(v.z); sW[r][c + 3] = tf32f(v.w);
        }
        __syncthreads();
#pragma unroll
        for (int sk = 0; sk < 32; sk += 8) {
            unsigned a0 = __float_as_uint(sA[mrow + g][sk + t]);
            unsigned a1 = __float_as_uint(sA[mrow + g + 8][sk + t]);
            unsigned a2 = __float_as_uint(sA[mrow + g][sk + t + 4]);
            unsigned a3 = __float_as_uint(sA[mrow + g + 8][sk + t + 4]);
#pragma unroll
            for (int j = 0; j < 6; j++) {
                int n0 = wn * 48 + j * 8;
                unsigned b0v = __float_as_uint(sW[sk + t][n0 + g]);
                unsigned b1v = __float_as_uint(sW[sk + t + 4][n0 + g]);
                mma8(acc[j], a0, a1, a2, a3, b0v, b1v);
            }
        }
        __syncthreads();
    }
    float* vp = g_pool + OF_VOLP;
    int r0 = row0 + mrow + g, r1 = r0 + 8;
#pragma unroll
    for (int j = 0; j < 6; j++) {
        int c = wn * 48 + j * 8 + 2 * t;
        float bx = pb[c], by = pb[c + 1];
        *(float2*)&vp[(size_t)r0 * 96 + c] = make_float2(acc[j].x + bx, acc[j].y + by);
        *(float2*)&vp[(size_t)r1 * 96 + c] = make_float2(acc[j].z + bx, acc[j].w + by);
    }
}

// ============================================================
// K7a: qkv GEMM (tf32 mma): XATT(64,96) @ qkv_w(96,288) + b
// block 256, grid rows/64, static smem
// ============================================================
__global__ __launch_bounds__(256) void k_qkv(
    const float* __restrict__ w, const float* __restrict__ bias)
{
    __shared__ float sA[64][36];
    __shared__ float sW[32][296];
    const int tid = threadIdx.x, warp = tid >> 5, lane = tid & 31;
    const int g = lane >> 2, t = lane & 3;
    const int wm = warp >> 1, wn = warp & 1;
    const int row0 = blockIdx.x * 64;
    const int mrow = wm * 16;
    const float* A = g_pool + OF_XATT;

    float4 acc[18];
#pragma unroll
    for (int j = 0; j < 18; j++) acc[j] = make_float4(0.f, 0.f, 0.f, 0.f);

    for (int kb = 0; kb < 96; kb += 32) {
#pragma unroll
        for (int i = 0; i < 2; i++) {
            int idx = tid * 2 + i; int r = idx >> 3, c = (idx & 7) * 4;
            float4 v = *(const float4*)(A + (size_t)(row0 + r) * 96 + kb + c);
            sA[r][c] = tf32f(v.x); sA[r][c + 1] = tf32f(v.y);
            sA[r][c + 2] = tf32f(v.z); sA[r][c + 3] = tf32f(v.w);
        }
#pragma unroll
        for (int i = 0; i < 9; i++) {
            int idx = tid + i * 256; int r = idx / 72, c = (idx % 72) * 4;
            float4 v = *(const float4*)(w + (size_t)(kb + r) * 288 + c);
            sW[r][c] = tf32f(v.x); sW[r][c + 1] = tf32f(v.y);
            sW[r][c + 2] = tf32f(v.z); sW[r][c + 3] = tf32f(v.w);
        }
        __syncthreads();
#pragma unroll
        for (int sk = 0; sk < 32; sk += 8) {
            unsigned a0 = __float_as_uint(sA[mrow + g][sk + t]);
            unsigned a1 = __float_as_uint(sA[mrow + g + 8][sk + t]);
            unsigned a2 = __float_as_uint(sA[mrow + g][sk + t + 4]);
            unsigned a3 = __float_as_uint(sA[mrow + g + 8][sk + t + 4]);
#pragma unroll
            for (int j = 0; j < 18; j++) {
                int n0 = wn * 144 + j * 8;
                unsigned b0v = __float_as_uint(sW[sk + t][n0 + g]);
                unsigned b1v = __float_as_uint(sW[sk + t + 4][n0 + g]);
                mma8(acc[j], a0, a1, a2, a3, b0v, b1v);
            }
        }
        __syncthreads();
    }
    float* Q = g_pool + OF_QKV;
    int r0 = row0 + mrow + g, r1 = r0 + 8;
#pragma unroll
    for (int j = 0; j < 18; j++) {
        int c = wn * 144 + j * 8 + 2 * t;
        float bx = bias[c], by = bias[c + 1];
        *(float2*)&Q[(size_t)r0 * 288 + c] = make_float2(acc[j].x + bx, acc[j].y + by);
        *(float2*)&Q[(size_t)r1 * 288 + c] = make_float2(acc[j].z + bx, acc[j].w + by);
    }
}

// ============================================================
// K7b: attention per window (round-1 scalar form)
// ============================================================
__global__ __launch_bounds__(256) void k_attn(const float* __restrict__ rpb)
{
    __shared__ float qS[64][17], kS[64][17], vS[64][17], pS[64][65];
    int tid = threadIdx.x;
    int win = blockIdx.x; int b = win >> 9;
    const float* qkv = g_pool + OF_QKV + (size_t)win * 64 * 288;
    float* out = g_pool + OF_AOUT + (size_t)win * 64 * 96;
    int warp = tid >> 5, lane = tid & 31;

    for (int hh = 0; hh < 6; hh++) {
        __syncthreads();
#pragma unroll
        for (int i = 0; i < 4; i++) {
            int idx = tid + i * 256; int n = idx >> 4, d = idx & 15;
            size_t base = (size_t)n * 288 + hh * 16 + d;
            qS[n][d] = qkv[base] * 0.25f;
            kS[n][d] = qkv[base + 96];
            vS[n][d] = qkv[base + 192] * g_pool[OF_GATE + b * 96 + hh * 16 + d];
        }
        __syncthreads();
        for (int rr = 0; rr < 8; rr++) {
            int n = warp * 8 + rr;
            int nd = n >> 4, nh = (n >> 2) & 3, nw = n & 3;
            int m0 = lane, m1 = lane + 32;
            float s0 = 0.f, s1 = 0.f;
#pragma unroll
            for (int d = 0; d < 16; d++) {
                float qv = qS[n][d];
                s0 += qv * kS[m0][d];
                s1 += qv * kS[m1][d];
            }
            {
                int md = m0 >> 4, mh = (m0 >> 2) & 3, mw = m0 & 3;
                s0 += rpb[((nd - md + 3) * 49 + (nh - mh + 3) * 7 + (nw - mw + 3)) * 6 + hh];
                md = m1 >> 4; mh = (m1 >> 2) & 3; mw = m1 & 3;
                s1 += rpb[((nd - md + 3) * 49 + (nh - mh + 3) * 7 + (nw - mw + 3)) * 6 + hh];
            }
            float mx = fmaxf(s0, s1);
#pragma unroll
            for (int o = 16; o; o >>= 1) mx = fmaxf(mx, __shfl_xor_sync(~0u, mx, o));
            float e0 = expf(s0 - mx), e1 = expf(s1 - mx);
            float sum = e0 + e1;
#pragma unroll
            for (int o = 16; o; o >>= 1) sum += __shfl_xor_sync(~0u, sum, o);
            float inv = 1.f / sum;
            pS[n][m0] = e0 * inv;
            pS[n][m1] = e1 * inv;
        }
        __syncthreads();
        {
            int n = tid >> 2, dg = tid & 3;
            float a0 = 0.f, a1 = 0.f, a2 = 0.f, a3 = 0.f;
#pragma unroll
            for (int m = 0; m < 64; m++) {
                float pm = pS[n][m];
                a0 += pm * vS[m][dg * 4 + 0];
                a1 += pm * vS[m][dg * 4 + 1];
                a2 += pm * vS[m][dg * 4 + 2];
                a3 += pm * vS[m][dg * 4 + 3];
            }
            size_t ob = (size_t)n * 96 + hh * 16 + dg * 4;
            out[ob + 0] = a0; out[ob + 1] = a1; out[ob + 2] = a2; out[ob + 3] = a3;
        }
    }
}

// ============================================================
// K8a: si stage 1
// ============================================================
__global__ __launch_bounds__(256) void k_si1(
    const float* __restrict__ w1, const float* __restrict__ b1)
{
    __shared__ float aS[64][97];
    __shared__ float wS[96 * 12];
    __shared__ float sb[64][12];
    int tid = threadIdx.x;
    int blk = blockIdx.x; int row0 = blk * 64;
    const float* A = g_pool + OF_AOUT;
    for (int i = tid; i < 96 * 12; i += 256) wS[i] = w1[i];
    for (int i = tid; i < 64 * 96; i += 256) {
        int r = i / 96, c = i % 96;
        aS[r][c] = A[(size_t)(row0 + r) * 96 + c];
    }
    __syncthreads();
    if (tid < 64) {
        float s[12];
#pragma unroll
        for (int j = 0; j < 12; j++) s[j] = b1[j];
        for (int c = 0; c < 96; c++) {
            float a = aS[tid][c];
#pragma unroll
            for (int j = 0; j < 12; j++) s[j] += a * wS[c * 12 + j];
        }
        float* o = g_pool + OF_S12 + (size_t)(row0 + tid) * 12;
#pragma unroll
        for (int j = 0; j < 12; j++) { o[j] = s[j]; sb[tid][j] = s[j]; }
    }
    __syncthreads();
    if (tid < 12) {
        float S = 0.f, Q = 0.f;
        for (int r = 0; r < 64; r++) { float v = sb[r][tid]; S += v; Q += v * v; }
        g_pool[OF_P12S + (size_t)blk * 12 + tid] = S;
        g_pool[OF_P12Q + (size_t)blk * 12 + tid] = Q;
    }
}

// ============================================================
// K8c: gate + multiply + partials
// ============================================================
__global__ __launch_bounds__(96) void k_gatemul(
    const float* __restrict__ w2, const float* __restrict__ b2)
{
    __shared__ float gb[64];
    int tid = threadIdx.x;
    int blk = blockIdx.x; int row0 = blk * 64; int b = row0 >> 15;
    if (tid < 64) {
        const float* s = g_pool + OF_S12 + (size_t)(row0 + tid) * 12;
        float a = b2[0];
#pragma unroll
        for (int j = 0; j < 12; j++) {
            float v = (s[j] - g_pool[OF_M2 + b * 12 + j]) * g_pool[OF_R2 + b * 12 + j];
            a += geluf(v) * w2[j];
        }
        gb[tid] = 1.f / (1.f + expf(-a));
    }
    __syncthreads();
    const float* vp = g_pool + OF_VOLP + (size_t)row0 * 96 + tid;
    float* yv = g_pool + OF_YV + (size_t)row0 * 96 + tid;
    float ss = 0.f, sq = 0.f;
    for (int r = 0; r < 64; r++) {
        float y = gb[r] * vp[(size_t)r * 96];
        yv[(size_t)r * 96] = y;
        ss += y; sq += y * y;
    }
    g_pool[OF_PYS + (size_t)blk * 96 + tid] = ss;
    g_pool[OF_PYQ + (size_t)blk * 96 + tid] = sq;
}

// ============================================================
// K9: final (tf32 mma): [LN(attn) | inorm(y)](64,192) @ w_proj(192,192) + b
// block 256, grid rows/64, dyn smem 75776B
// ============================================================
__global__ __launch_bounds__(256) void k_final(
    const float* __restrict__ wp, const float* __restrict__ bp,
    const float* __restrict__ ga, const float* __restrict__ ba,
    float* __restrict__ out)
{
    extern __shared__ float sm[];
    float (*sA)[196] = (float(*)[196])sm;                  // 64x196
    float (*sW)[200] = (float(*)[200])(sm + 64 * 196);     // 32x200
    const int tid = threadIdx.x, warp = tid >> 5, lane = tid & 31;
    const int g = lane >> 2, t = lane & 3;
    const int wm = warp >> 1, wn = warp & 1;
    const int row0 = blockIdx.x * 64; const int b = row0 >> 15;
    const int mrow = wm * 16;
    const float* A = g_pool + OF_AOUT;
    const float* Y = g_pool + OF_YV;

    // prologue: LN(attn) -> sA[:, 0:96], inorm(y) -> sA[:, 96:192]
    for (int it = 0; it < 8; it++) {
        int r = warp * 8 + it;
        int row = row0 + r;
        float s = 0.f, q = 0.f;
        float vals[3];
#pragma unroll
        for (int i = 0; i < 3; i++) {
            vals[i] = A[(size_t)row * 96 + lane + 32 * i];
            s += vals[i]; q += vals[i] * vals[i];
        }
#pragma unroll
        for (int o = 16; o; o >>= 1) { s += __shfl_xor_sync(~0u, s, o); q += __shfl_xor_sync(~0u, q, o); }
        float m = s * (1.f / 96.f);
        float rs = rsqrtf(fmaxf(q * (1.f / 96.f) - m * m, 0.f) + EPS);
#pragma unroll
        for (int i = 0; i < 3; i++) {
            int c = lane + 32 * i;
            sA[r][c] = tf32f((vals[i] - m) * rs * ga[c] + ba[c]);
        }
#pragma unroll
        for (int i = 0; i < 3; i++) {
            int c = lane + 32 * i;
            float v = (Y[(size_t)row * 96 + c] - g_pool[OF_M3 + b * 96 + c]) * g_pool[OF_R3 + b * 96 + c];
            sA[r][96 + c] = tf32f(v);
        }
    }
    __syncthreads();

    float4 acc[12];
#pragma unroll
    for (int j = 0; j < 12; j++) acc[j] = make_float4(0.f, 0.f, 0.f, 0.f);

    for (int kb = 0; kb < 192; kb += 32) {
#pragma unroll
        for (int i = 0; i < 6; i++) {
            int idx = tid + i * 256; int r = idx / 48, c = (idx % 48) * 4;
            float4 v = *(const float4*)(wp + (size_t)(kb + r) * 192 + c);
            sW[r][c] = tf32f(v.x); sW[r][c + 1] = tf32f(v.y);
            sW[r][c + 2] = tf32f(v.z); sW[r][c + 3] = tf32f(v.w);
        }
        __syncthreads();
#pragma unroll
        for (int sk = 0; sk < 32; sk += 8) {
            unsigned a0 = __float_as_uint(sA[mrow + g][kb + sk + t]);
            unsigned a1 = __float_as_uint(sA[mrow + g + 8][kb + sk + t]);
            unsigned a2 = __float_as_uint(sA[mrow + g][kb + sk + t + 4]);
            unsigned a3 = __float_as_uint(sA[mrow + g + 8][kb + sk + t + 4]);
#pragma unroll
            for (int j = 0; j < 12; j++) {
                int n0 = wn * 96 + j * 8;
                unsigned b0v = __float_as_uint(sW[sk + t][n0 + g]);
                unsigned b1v = __float_as_uint(sW[sk + t + 4][n0 + g]);
                mma8(acc[j], a0, a1, a2, a3, b0v, b1v);
            }
        }
        __syncthreads();
    }
    int r0 = row0 + mrow + g, r1 = r0 + 8;
#pragma unroll
    for (int j = 0; j < 12; j++) {
        int c = wn * 96 + j * 8 + 2 * t;
        float bx = bp[c], by = bp[c + 1];
        *(float2*)&out[(size_t)r0 * 192 + c] = make_float2(acc[j].x + bx, acc[j].y + by);
        *(float2*)&out[(size_t)r1 * 192 + c] = make_float2(acc[j].z + bx, acc[j].w + by);
    }
}

// ============================================================
// host launcher
// ============================================================
extern "C" void kernel_launch(void* const* d_in, const int* in_sizes, int n_in,
                              void* d_out, int out_size)
{
    const float* x       = (const float*)d_in[0];
    const float* w_pattn = (const float*)d_in[1];
    const float* b_pattn = (const float*)d_in[2];
    const float* g_aln   = (const float*)d_in[3];
    const float* b_aln   = (const float*)d_in[4];
    const float* w_pcnn  = (const float*)d_in[5];
    const float* b_pcnn  = (const float*)d_in[6];
    const float* g_cln   = (const float*)d_in[7];
    const float* b_cln   = (const float*)d_in[8];
    const float* dw_w    = (const float*)d_in[9];
    const float* dw_b    = (const float*)d_in[10];
    const float* ci_w1   = (const float*)d_in[11];
    const float* ci_b1   = (const float*)d_in[12];
    const float* ci_w2   = (const float*)d_in[13];
    const float* ci_b2   = (const float*)d_in[14];
    const float* pj_w    = (const float*)d_in[15];
    const float* pj_b    = (const float*)d_in[16];
    const float* qkv_w   = (const float*)d_in[17];
    const float* qkv_b   = (const float*)d_in[18];
    const float* si_w1   = (const float*)d_in[19];
    const float* si_b1   = (const float*)d_in[20];
    const float* si_w2   = (const float*)d_in[21];
    const float* si_b2   = (const float*)d_in[22];
    const float* g_anorm = (const float*)d_in[23];
    const float* b_anorm = (const float*)d_in[24];
    const float* w_proj  = (const float*)d_in[25];
    const float* b_proj  = (const float*)d_in[26];
    const float* rpb     = (const float*)d_in[27];

    const int Bwin = in_sizes[0] / (64 * 192);   // 2048
    const int rows = Bwin * 64;                  // 131072
    const int nb   = Bwin / 512;                 // 4

    static int attr_done = 0;
    if (!attr_done) {
        cudaFuncSetAttribute(k_embed, cudaFuncAttributeMaxDynamicSharedMemorySize, 73728);
        cudaFuncSetAttribute(k_final, cudaFuncAttributeMaxDynamicSharedMemorySize, 75776);
        attr_done = 1;
    }

    k_embed<<<rows / 64, 256, 73728>>>(x, w_pattn, b_pattn, g_aln, b_aln,
                                       w_pcnn, b_pcnn, g_cln, b_cln);
    k_dwconv<<<nb * 1024, 192>>>(dw_w, dw_b);
    k_redstats<<<nb * 192, 128>>>(OF_PCS, OF_PCQ, 1024, 192, 1.f / 32768.f, OF_M1, OF_R1);
    k_normgelu<<<nb * 1024, 192>>>();
    k_redmean<<<nb * 192, 128>>>(OF_PPOOL, 1024, 192, 1.f / 32768.f, OF_POOLED);
    k_ci<<<1, 96>>>(ci_w1, ci_b1, ci_w2, ci_b2, nb);
    k_pj<<<rows / 64, 256>>>(pj_w, pj_b);
    k_qkv<<<rows / 64, 256>>>(qkv_w, qkv_b);
    k_attn<<<Bwin, 256>>>(rpb);
    k_si1<<<rows / 64, 256>>>(si_w1, si_b1);
    k_redstats<<<nb * 12, 128>>>(OF_P12S, OF_P12Q, 512, 12, 1.f / 32768.f, OF_M2, OF_R2);
    k_gatemul<<<rows / 64, 96>>>(si_w2, si_b2);
    k_redstats<<<nb * 96, 128>>>(OF_PYS, OF_PYQ, 512, 96, 1.f / 32768.f, OF_M3, OF_R3);
    k_final<<<rows / 64, 256, 75776>>>(w_proj, b_proj, g_anorm, b_anorm, (float*)d_out);
}